// round 6
// baseline (speedup 1.0000x reference)
#include <cuda_runtime.h>

#define CC 1024

// ---- device scratch (static __device__ arrays; allocation is forbidden) ----
__device__ float g_L[8 * 2048 * CC];
__device__ float g_S[8 * 2048 * CC];
__device__ float g_vbuf[8 * 1024 * CC];
__device__ float g_Amul[8 * 1024 * CC];
__device__ float g_Z[4096 * CC];
__device__ float g_WqT[CC * CC];
__device__ float g_WvT[CC * CC];
__device__ float g_WcT[CC * CC];
__device__ float g_ow1[CC * CC];
__device__ float g_ow2[CC * CC];
__device__ float g_ow1T[CC * CC];
__device__ float g_ow2T[CC * CC];
__device__ float g_Utmp[CC * CC];
__device__ float g_probe1[CC];
__device__ float g_probe2[CC];
__device__ float g_rowsq[CC];
__device__ float g_ss;

// ---- threefry2x32 (exact JAX) -> normal probes ----
__device__ __forceinline__ unsigned rotl32(unsigned x, int d) { return (x << d) | (x >> (32 - d)); }

__device__ void threefry2x32(unsigned k0, unsigned k1, unsigned x0, unsigned x1,
                             unsigned* o0, unsigned* o1) {
    unsigned ks[3] = {k0, k1, k0 ^ k1 ^ 0x1BD11BDAu};
    const int rot0[4] = {13, 15, 26, 6};
    const int rot1[4] = {17, 29, 16, 24};
    x0 += ks[0]; x1 += ks[1];
    #pragma unroll
    for (int g = 0; g < 5; g++) {
        if ((g & 1) == 0) {
            #pragma unroll
            for (int j = 0; j < 4; j++) { x0 += x1; x1 = rotl32(x1, rot0[j]); x1 ^= x0; }
        } else {
            #pragma unroll
            for (int j = 0; j < 4; j++) { x0 += x1; x1 = rotl32(x1, rot1[j]); x1 ^= x0; }
        }
        x0 += ks[(g + 1) % 3];
        x1 += ks[(g + 2) % 3] + (unsigned)(g + 1);
    }
    *o0 = x0; *o1 = x1;
}

__device__ float erfinv_f32(float x) {  // XLA ErfInv32 (Giles)
    float w = -log1pf(-x * x), p;
    if (w < 5.0f) {
        w -= 2.5f;
        p = 2.81022636e-08f;
        p = fmaf(p, w, 3.43273939e-07f);  p = fmaf(p, w, -3.5233877e-06f);
        p = fmaf(p, w, -4.39150654e-06f); p = fmaf(p, w, 0.00021858087f);
        p = fmaf(p, w, -0.00125372503f);  p = fmaf(p, w, -0.00417768164f);
        p = fmaf(p, w, 0.246640727f);     p = fmaf(p, w, 1.50140941f);
    } else {
        w = sqrtf(w) - 3.0f;
        p = -0.000200214257f;
        p = fmaf(p, w, 0.000100950558f);  p = fmaf(p, w, 0.00134934322f);
        p = fmaf(p, w, -0.00367342844f);  p = fmaf(p, w, 0.00573950773f);
        p = fmaf(p, w, -0.0076224613f);   p = fmaf(p, w, 0.00943887047f);
        p = fmaf(p, w, 1.00167406f);      p = fmaf(p, w, 2.83297682f);
    }
    return p * x;
}

__device__ float bits_to_normal(unsigned b) {
    float f = __uint_as_float((b >> 9) | 0x3f800000u) - 1.0f;   // [0,1)
    const float lo = -0.99999994f;                               // nextafter(-1,0)
    float u = fmaxf(lo, f * 2.0f + lo);                          // (1 - lo) rounds to 2.0f in f32
    return 1.41421356f * erfinv_f32(u);
}

// Partitionable threefry (modern JAX default): element i <- threefry2x32(key, (i>>32, i&0xffffffff)),
// 32-bit draws fold the two outputs with XOR.
__global__ void probes_kernel() {
    int i = threadIdx.x;  // 1024 threads
    unsigned a, b;
    threefry2x32(0u, 101u, 0u, (unsigned)i, &a, &b);
    g_probe1[i] = bits_to_normal(a ^ b);
    threefry2x32(0u, 102u, 0u, (unsigned)i, &a, &b);
    g_probe2[i] = bits_to_normal(a ^ b);
}

// ---- fast_polar pieces ----
__global__ void gemv_sq_kernel(const float* __restrict__ U, const float* __restrict__ v) {
    int r = blockIdx.x;
    const float* u = U + (size_t)r * CC;
    float acc = 0.f;
    for (int c = threadIdx.x; c < CC; c += 256) acc += u[c] * v[c];
    #pragma unroll
    for (int o = 16; o > 0; o >>= 1) acc += __shfl_xor_sync(0xffffffffu, acc, o);
    __shared__ float sm[8];
    if ((threadIdx.x & 31) == 0) sm[threadIdx.x >> 5] = acc;
    __syncthreads();
    if (threadIdx.x == 0) {
        float t = 0.f;
        #pragma unroll
        for (int i = 0; i < 8; i++) t += sm[i];
        g_rowsq[r] = t * t;
    }
}

__global__ void reduce_ss_kernel() {
    __shared__ float sm[512];
    int t = threadIdx.x;
    sm[t] = g_rowsq[t] + g_rowsq[t + 512];
    __syncthreads();
    for (int s = 256; s > 0; s >>= 1) { if (t < s) sm[t] += sm[t + s]; __syncthreads(); }
    if (t == 0) g_ss = sqrtf(sm[0]) + 1e-8f;
}

// dst = 0.5*(src + ((2I - src/s)/s)^T)
__global__ void polar_update_kernel(const float* __restrict__ src, float* __restrict__ dst) {
    int idx = blockIdx.x * 256 + threadIdx.x;
    int i = idx >> 10, j = idx & (CC - 1);
    float s = g_ss;
    float diag = (i == j) ? 2.0f : 0.0f;
    dst[idx] = 0.5f * (src[idx] + (diag - src[(size_t)j * CC + i] / s) / s);
}

// ---- data movement ----
__global__ void transpose_kernel(const float* __restrict__ in, float* __restrict__ out) {
    __shared__ float t[32][33];
    int bx = blockIdx.x * 32, by = blockIdx.y * 32;
    int x = threadIdx.x, y = threadIdx.y;  // 32x8
    #pragma unroll
    for (int k = 0; k < 32; k += 8) t[y + k][x] = in[(size_t)(by + y + k) * CC + bx + x];
    __syncthreads();
    #pragma unroll
    for (int k = 0; k < 32; k += 8) out[(size_t)(bx + y + k) * CC + by + x] = t[x][y + k];
}

__global__ void init_head_kernel(const float* __restrict__ idn) {
    int b = blockIdx.x;
    for (int c = threadIdx.x; c < CC; c += 256) g_L[(size_t)b * 2048 * CC + c] = idn[c];
}

__global__ void copy_rows_kernel(const float* __restrict__ S, int sn, int soff, int sstr, int scnt,
                                 float* __restrict__ D, int dn, int doff, int dstr) {
    int r = blockIdx.x;
    int b = r / scnt, i = r % scnt;
    const float* s = S + ((size_t)b * sn + soff + (size_t)i * sstr) * CC;
    float* d = D + ((size_t)b * dn + doff + (size_t)i * dstr) * CC;
    for (int c = threadIdx.x; c < CC; c += 256) d[c] = s[c];
}

__global__ void mult_kernel() {
    int r = blockIdx.x;                 // 0..8191
    int b = r >> 10, t = r & 1023;
    const float* s = g_S + ((size_t)b * 2048 + 1 + t) * CC;
    const float* v = g_vbuf + (size_t)r * CC;
    float* a = g_Amul + (size_t)r * CC;
    for (int c = threadIdx.x; c < CC; c += 256) a[c] = s[c] * v[c];
}

// range_norm each row of Z, scatter via (off,stride) mapping
__global__ void rownorm_kernel(const float* __restrict__ Z,
                               float* __restrict__ Ob, int on, int ooff, int ostr, int ocnt) {
    int r = blockIdx.x;
    const float* z = Z + (size_t)r * CC;
    float mn = 1e30f, mx = -1e30f;
    for (int c = threadIdx.x; c < CC; c += 256) {
        float v = z[c];
        mn = fminf(mn, v); mx = fmaxf(mx, v);
    }
    #pragma unroll
    for (int o = 16; o > 0; o >>= 1) {
        mn = fminf(mn, __shfl_xor_sync(0xffffffffu, mn, o));
        mx = fmaxf(mx, __shfl_xor_sync(0xffffffffu, mx, o));
    }
    __shared__ float smn[8], smx[8];
    int w = threadIdx.x >> 5, l = threadIdx.x & 31;
    if (l == 0) { smn[w] = mn; smx[w] = mx; }
    __syncthreads();
    if (threadIdx.x == 0) {
        float a = smn[0], b2 = smx[0];
        #pragma unroll
        for (int i = 1; i < 8; i++) { a = fminf(a, smn[i]); b2 = fmaxf(b2, smx[i]); }
        smn[0] = a; smx[0] = b2;
    }
    __syncthreads();
    mn = smn[0]; mx = smx[0];
    float inv = 2.0f / (mx - mn + 1e-8f);
    int b = r / ocnt, i = r % ocnt;
    float* o = Ob + ((size_t)b * on + ooff + (size_t)i * ostr) * CC;
    for (int c = threadIdx.x; c < CC; c += 256) o[c] = (z[c] - mn) * inv - 1.0f;
}

// ---- SGEMM: rows of A and C addressed via (base,n,off,stride,cnt): row r ->
//      b=r/cnt, i=r%cnt, ptr = base + (b*n + off + i*stride)*1024 ----
__global__ __launch_bounds__(256)
void sgemm_kernel(int M,
                  const float* __restrict__ Ab, int an, int aoff, int astr, int acnt,
                  const float* __restrict__ Bm,
                  float* __restrict__ Ob, int on, int ooff, int ostr, int ocnt,
                  int beta) {
    __shared__ __align__(16) float As[8][128];
    __shared__ __align__(16) float Bs[8][128];
    const int tid = threadIdx.x;
    const int tx = tid & 15, ty = tid >> 4;
    const int bn = blockIdx.x * 128, bm = blockIdx.y * 128;

    int la_r = tid >> 1, la_k = (tid & 1) * 4;
    int ar = bm + la_r; if (ar > M - 1) ar = M - 1;
    int ab2 = ar / acnt, ai = ar % acnt;
    const float* aptr = Ab + ((size_t)ab2 * an + aoff + (size_t)ai * astr) * 1024 + la_k;

    int lb_k = tid >> 5, lb_n = (tid & 31) * 4;
    const float* bptr = Bm + (size_t)lb_k * 1024 + bn + lb_n;

    float acc[8][8];
    #pragma unroll
    for (int i = 0; i < 8; i++)
        #pragma unroll
        for (int j = 0; j < 8; j++) acc[i][j] = 0.f;

    for (int kb = 0; kb < 1024; kb += 8) {
        float4 av = *(const float4*)(aptr + kb);
        float4 bv = *(const float4*)(bptr + (size_t)kb * 1024);
        __syncthreads();
        As[la_k + 0][la_r] = av.x; As[la_k + 1][la_r] = av.y;
        As[la_k + 2][la_r] = av.z; As[la_k + 3][la_r] = av.w;
        *(float4*)&Bs[lb_k][lb_n] = bv;
        __syncthreads();
        #pragma unroll
        for (int k = 0; k < 8; k++) {
            float ra[8], rb[8];
            *(float4*)&ra[0] = *(const float4*)&As[k][ty * 8];
            *(float4*)&ra[4] = *(const float4*)&As[k][ty * 8 + 4];
            *(float4*)&rb[0] = *(const float4*)&Bs[k][tx * 8];
            *(float4*)&rb[4] = *(const float4*)&Bs[k][tx * 8 + 4];
            #pragma unroll
            for (int i = 0; i < 8; i++)
                #pragma unroll
                for (int j = 0; j < 8; j++) acc[i][j] = fmaf(ra[i], rb[j], acc[i][j]);
        }
    }
    #pragma unroll
    for (int i = 0; i < 8; i++) {
        int r = bm + ty * 8 + i;
        if (r < M) {
            int ob = r / ocnt, oi = r % ocnt;
            float* op = Ob + ((size_t)ob * on + ooff + (size_t)oi * ostr) * 1024 + bn + tx * 8;
            float4 c0, c1;
            if (beta) {
                c0 = *(const float4*)op; c1 = *(const float4*)(op + 4);
                c0.x += acc[i][0]; c0.y += acc[i][1]; c0.z += acc[i][2]; c0.w += acc[i][3];
                c1.x += acc[i][4]; c1.y += acc[i][5]; c1.z += acc[i][6]; c1.w += acc[i][7];
            } else {
                c0 = make_float4(acc[i][0], acc[i][1], acc[i][2], acc[i][3]);
                c1 = make_float4(acc[i][4], acc[i][5], acc[i][6], acc[i][7]);
            }
            *(float4*)op = c0; *(float4*)(op + 4) = c1;
        }
    }
}

static inline void gemm(const float* A, int an, int aoff, int astr, int acnt,
                        const float* Bm,
                        float* O, int on, int ooff, int ostr, int ocnt,
                        int M, int beta) {
    dim3 grid(CC / 128, (M + 127) / 128);
    sgemm_kernel<<<grid, 256>>>(M, A, an, aoff, astr, acnt, Bm, O, on, ooff, ostr, ocnt, beta);
}

extern "C" void kernel_launch(void* const* d_in, const int* in_sizes, int n_in,
                              void* d_out, int out_size) {
    (void)in_sizes; (void)n_in; (void)out_size;
    const float* x   = (const float*)d_in[0];
    const float* Wq  = (const float*)d_in[1];
    const float* Wv  = (const float*)d_in[2];
    const float* Wc  = (const float*)d_in[3];
    const float* idn = (const float*)d_in[4];
    const float* P1  = (const float*)d_in[5];
    const float* P2  = (const float*)d_in[6];
    float* out = (float*)d_out;

    float *pL, *pS, *pV, *pA, *pZ, *pWqT, *pWvT, *pWcT;
    float *pow1, *pow2, *pow1T, *pow2T, *pUt, *ppr1, *ppr2;
    cudaGetSymbolAddress((void**)&pL,    g_L);
    cudaGetSymbolAddress((void**)&pS,    g_S);
    cudaGetSymbolAddress((void**)&pV,    g_vbuf);
    cudaGetSymbolAddress((void**)&pA,    g_Amul);
    cudaGetSymbolAddress((void**)&pZ,    g_Z);
    cudaGetSymbolAddress((void**)&pWqT,  g_WqT);
    cudaGetSymbolAddress((void**)&pWvT,  g_WvT);
    cudaGetSymbolAddress((void**)&pWcT,  g_WcT);
    cudaGetSymbolAddress((void**)&pow1,  g_ow1);
    cudaGetSymbolAddress((void**)&pow2,  g_ow2);
    cudaGetSymbolAddress((void**)&pow1T, g_ow1T);
    cudaGetSymbolAddress((void**)&pow2T, g_ow2T);
    cudaGetSymbolAddress((void**)&pUt,   g_Utmp);
    cudaGetSymbolAddress((void**)&ppr1,  g_probe1);
    cudaGetSymbolAddress((void**)&ppr2,  g_probe2);

    // 1) probes (partitionable threefry layout)
    probes_kernel<<<1, 1024>>>();

    // 2) fast_polar(P1)->ow1, fast_polar(P2)->ow2 (2 iterations each)
    gemv_sq_kernel<<<CC, 256>>>(P1, ppr1);
    reduce_ss_kernel<<<1, 512>>>();
    polar_update_kernel<<<CC * CC / 256, 256>>>(P1, pUt);
    gemv_sq_kernel<<<CC, 256>>>(pUt, ppr1);
    reduce_ss_kernel<<<1, 512>>>();
    polar_update_kernel<<<CC * CC / 256, 256>>>(pUt, pow1);

    gemv_sq_kernel<<<CC, 256>>>(P2, ppr2);
    reduce_ss_kernel<<<1, 512>>>();
    polar_update_kernel<<<CC * CC / 256, 256>>>(P2, pUt);
    gemv_sq_kernel<<<CC, 256>>>(pUt, ppr2);
    reduce_ss_kernel<<<1, 512>>>();
    polar_update_kernel<<<CC * CC / 256, 256>>>(pUt, pow2);

    // 3) transposes (GEMM consumes B as [k][n] row-major = W^T)
    dim3 tg(32, 32), tb(32, 8);
    transpose_kernel<<<tg, tb>>>(Wq, pWqT);
    transpose_kernel<<<tg, tb>>>(Wv, pWvT);
    transpose_kernel<<<tg, tb>>>(Wc, pWcT);
    transpose_kernel<<<tg, tb>>>(pow1, pow1T);
    transpose_kernel<<<tg, tb>>>(pow2, pow2T);

    // 4) seq head + projections: q -> L level-0 slots 1..1024, v -> vbuf
    init_head_kernel<<<8, 256>>>(idn);
    gemm(x, 1024, 0, 1, 1024, pWqT, pL, 2048, 1, 1, 1024, 8192, 0);
    gemm(x, 1024, 0, 1, 1024, pWvT, pV, 1024, 0, 1, 1024, 8192, 0);

    // 5) scan tree (exact jax.lax.associative_scan recursion, iterative form)
    static const int NL = 11;
    static const int nlev[NL] = {1025, 512, 256, 128, 64, 32, 16, 8, 4, 2, 1};
    static const int olev[NL] = {0, 1025, 1537, 1793, 1921, 1985, 2017, 2033, 2041, 2045, 2047};

    // down: L[l+1][i] = combine(L[l][2i], L[l][2i+1])
    for (int l = 0; l < NL - 1; l++) {
        int cnt = nlev[l] / 2, M = 8 * cnt;
        gemm(pL, 2048, olev[l],     2, cnt, pow1T, pZ, cnt, 0, 1, cnt, M, 0);
        gemm(pL, 2048, olev[l] + 1, 2, cnt, pow2T, pZ, cnt, 0, 1, cnt, M, 1);
        rownorm_kernel<<<M, 256>>>(pZ, pL, 2048, olev[l + 1], 1, cnt);
    }

    // up: S[10] = L[10]; then S[l][0]=L[l][0], S[l][2i+1]=S[l+1][i],
    //     S[l][2i+2]=combine(S[l+1][i], L[l][2i+2])
    copy_rows_kernel<<<8, 256>>>(pL, 2048, olev[10], 1, 1, pS, 2048, olev[10], 1);
    for (int l = NL - 2; l >= 0; l--) {
        int ce = (nlev[l] - 1) / 2;
        copy_rows_kernel<<<8, 256>>>(pL, 2048, olev[l], 1, 1, pS, 2048, olev[l], 1);
        copy_rows_kernel<<<8 * nlev[l + 1], 256>>>(pS, 2048, olev[l + 1], 1, nlev[l + 1],
                                                   pS, 2048, olev[l] + 1, 2);
        if (ce > 0) {
            int M = 8 * ce;
            gemm(pS, 2048, olev[l + 1], 1, ce, pow1T, pZ, ce, 0, 1, ce, M, 0);
            gemm(pL, 2048, olev[l] + 2, 2, ce, pow2T, pZ, ce, 0, 1, ce, M, 1);
            rownorm_kernel<<<M, 256>>>(pZ, pS, 2048, olev[l] + 2, 2, ce);
        }
    }

    // 6) Y = (scanned * v) @ Wc^T
    mult_kernel<<<8192, 256>>>();
    gemm(pA, 1024, 0, 1, 1024, pWcT, out, 1024, 0, 1, 1024, 8192, 0);
}